// round 1
// baseline (speedup 1.0000x reference)
#include <cuda_runtime.h>
#include <math.h>

#define H 1024
#define TWO_H 2048
#define S_LEN 2048
#define D_EMB 512
#define L_CLS 16
#define VOCAB 50257
#define COMB_IN 2576   // D + 2H + L
#define OUT_IN 1552    // H + L + D

// ---- scratch offsets (floats) in one device array ----
#define OFF_V     0        // [2048]  attn_W^T @ h
#define OFF_CTX   2048     // [2048]  context
#define OFF_SLOG  4096     // [2048]  score logits -> scores (in place)
#define OFF_X1    6144     // [1024]
#define OFF_X2    7168     // [1024]
#define OFF_X3    8192     // [1024]
#define OFF_GI    9216     // [3072]
#define OFF_GH    12288    // [3072]
#define OFF_XO    15360    // [1552]  [h_new, nlg, emb]
#define OFF_PMAX  16912    // [64]
#define OFF_PSUM  16976    // [64]
#define OFF_LOGZ  17040    // [1]
#define SCRATCH_SZ 17056

__device__ __align__(16) float g_scratch[SCRATCH_SZ];

// ---------------------------------------------------------------------------
// zero the atomic accumulators (v, ctx)
__global__ void k_zero(float* s) {
    int i = blockIdx.x * blockDim.x + threadIdx.x;
    if (i < 4096) s[i] = 0.f;
}

// ---------------------------------------------------------------------------
// y[j] += sum_{h in chunk} W[h*TWO_H + j] * x[h]   (column reduction, split-K)
// grid = (ncols/256, nchunks), block = 256, chunk = 128 rows
__global__ void k_colmv(const float* __restrict__ W, const float* __restrict__ x,
                        float* __restrict__ y) {
    __shared__ float xs[128];
    int j  = blockIdx.x * blockDim.x + threadIdx.x;
    int h0 = blockIdx.y * 128;
    if (threadIdx.x < 128) xs[threadIdx.x] = x[h0 + threadIdx.x];
    __syncthreads();
    float acc = 0.f;
    const float* Wp = W + (size_t)h0 * TWO_H + j;
#pragma unroll 8
    for (int h = 0; h < 128; ++h) acc = fmaf(Wp[(size_t)h * TWO_H], xs[h], acc);
    atomicAdd(&y[j], acc);
}

// ---------------------------------------------------------------------------
// warp-per-row GEMV: y[r] = W[r,:]·x (+ b[r]) (optionally relu). x -> SMEM.
template<int NC, bool RELU>
__global__ void k_rowmv(const float* __restrict__ W, const float* __restrict__ x,
                        const float* __restrict__ b, float* __restrict__ y, int nrows) {
    __shared__ __align__(16) float xs[NC];
    for (int i = threadIdx.x; i < NC / 4; i += blockDim.x)
        ((float4*)xs)[i] = ((const float4*)x)[i];
    __syncthreads();
    int lane = threadIdx.x & 31;
    int row  = blockIdx.x * (blockDim.x >> 5) + (threadIdx.x >> 5);
    if (row >= nrows) return;
    const float4* Wr = (const float4*)(W + (size_t)row * NC);
    float acc = 0.f;
#pragma unroll 4
    for (int i = lane; i < NC / 4; i += 32) {
        float4 w = Wr[i], v = ((const float4*)xs)[i];
        acc += w.x * v.x + w.y * v.y + w.z * v.z + w.w * v.w;
    }
#pragma unroll
    for (int o = 16; o; o >>= 1) acc += __shfl_xor_sync(0xffffffffu, acc, o);
    if (lane == 0) {
        float r = acc + (b ? b[row] : 0.f);
        y[row] = RELU ? fmaxf(r, 0.f) : r;
    }
}

// ---------------------------------------------------------------------------
// comb layer: x = [emb(token), ctx, nlg] built straight into SMEM, then GEMV+relu
__global__ void k_comb(const float* __restrict__ W, const float* __restrict__ b,
                       const float* __restrict__ emb_table, const int* __restrict__ tok,
                       const float* __restrict__ ctx, const float* __restrict__ nlg,
                       float* __restrict__ y) {
    __shared__ __align__(16) float xs[COMB_IN];
    int t = *tok;
    for (int i = threadIdx.x; i < COMB_IN; i += blockDim.x) {
        float v;
        if (i < D_EMB)               v = emb_table[(size_t)t * D_EMB + i];
        else if (i < D_EMB + TWO_H)  v = ctx[i - D_EMB];
        else                         v = nlg[i - (D_EMB + TWO_H)];
        xs[i] = v;
    }
    __syncthreads();
    int lane = threadIdx.x & 31;
    int row  = blockIdx.x * (blockDim.x >> 5) + (threadIdx.x >> 5);
    if (row >= H) return;
    const float4* Wr = (const float4*)(W + (size_t)row * COMB_IN);
    float acc = 0.f;
#pragma unroll 4
    for (int i = lane; i < COMB_IN / 4; i += 32) {
        float4 w = Wr[i], v = ((const float4*)xs)[i];
        acc += w.x * v.x + w.y * v.y + w.z * v.z + w.w * v.w;
    }
#pragma unroll
    for (int o = 16; o; o >>= 1) acc += __shfl_xor_sync(0xffffffffu, acc, o);
    if (lane == 0) y[row] = fmaxf(acc + b[row], 0.f);
}

// ---------------------------------------------------------------------------
// softmax over S=2048 logits (1 block, 1024 threads); writes scores in place
// and attention weights to output.
__global__ void k_softmax(float* __restrict__ sl, float* __restrict__ attn_out) {
    __shared__ float red[32];
    __shared__ float bcast;
    int t = threadIdx.x;
    float a0 = sl[t], a1 = sl[t + 1024];
    float m = fmaxf(a0, a1);
#pragma unroll
    for (int o = 16; o; o >>= 1) m = fmaxf(m, __shfl_xor_sync(0xffffffffu, m, o));
    if ((t & 31) == 0) red[t >> 5] = m;
    __syncthreads();
    if (t == 0) { float v = red[0]; for (int w = 1; w < 32; w++) v = fmaxf(v, red[w]); bcast = v; }
    __syncthreads();
    float M = bcast;
    float e0 = expf(a0 - M), e1 = expf(a1 - M);
    float s = e0 + e1;
#pragma unroll
    for (int o = 16; o; o >>= 1) s += __shfl_xor_sync(0xffffffffu, s, o);
    if ((t & 31) == 0) red[t >> 5] = s;
    __syncthreads();
    if (t == 0) { float v = 0.f; for (int w = 0; w < 32; w++) v += red[w]; bcast = v; }
    __syncthreads();
    float inv = 1.f / bcast;
    float s0 = e0 * inv, s1 = e1 * inv;
    sl[t] = s0;           sl[t + 1024] = s1;
    attn_out[t] = s0;     attn_out[t + 1024] = s1;
}

// ---------------------------------------------------------------------------
// GRU gates + build the output-GEMV input vector xo = [h_new, nlg, emb]
__global__ void k_gate(const float* __restrict__ gi, const float* __restrict__ gh,
                       const float* __restrict__ hid, const float* __restrict__ nlg,
                       const float* __restrict__ emb_table, const int* __restrict__ tok,
                       float* __restrict__ xo, float* __restrict__ hout) {
    int j = threadIdx.x;  // 1024
    float r = 1.f / (1.f + expf(-(gi[j] + gh[j])));
    float z = 1.f / (1.f + expf(-(gi[H + j] + gh[H + j])));
    float n = tanhf(gi[2 * H + j] + r * gh[2 * H + j]);
    float hn = (1.f - z) * n + z * hid[j];
    xo[j] = hn;
    hout[j] = hn;
    if (j < L_CLS) xo[H + j] = nlg[j];
    if (j < D_EMB) xo[H + L_CLS + j] = emb_table[(size_t)(*tok) * D_EMB + j];
}

// ---------------------------------------------------------------------------
// log-softmax reductions over VOCAB
__global__ void k_red1(const float* __restrict__ logits, float* __restrict__ pmax,
                       float* __restrict__ psum) {
    __shared__ float red[8];
    __shared__ float Msh;
    const int chunk = (VOCAB + 63) / 64;
    int s = blockIdx.x * chunk;
    int e = min(s + chunk, VOCAB);
    float m = -INFINITY;
    for (int i = s + threadIdx.x; i < e; i += blockDim.x) m = fmaxf(m, logits[i]);
#pragma unroll
    for (int o = 16; o; o >>= 1) m = fmaxf(m, __shfl_xor_sync(0xffffffffu, m, o));
    if ((threadIdx.x & 31) == 0) red[threadIdx.x >> 5] = m;
    __syncthreads();
    if (threadIdx.x == 0) { float v = red[0]; for (int w = 1; w < 8; w++) v = fmaxf(v, red[w]); Msh = v; }
    __syncthreads();
    float M = Msh;
    float sum = 0.f;
    for (int i = s + threadIdx.x; i < e; i += blockDim.x) sum += expf(logits[i] - M);
#pragma unroll
    for (int o = 16; o; o >>= 1) sum += __shfl_xor_sync(0xffffffffu, sum, o);
    if ((threadIdx.x & 31) == 0) red[threadIdx.x >> 5] = sum;
    __syncthreads();
    if (threadIdx.x == 0) {
        float v = 0.f; for (int w = 0; w < 8; w++) v += red[w];
        pmax[blockIdx.x] = M; psum[blockIdx.x] = v;
    }
}

__global__ void k_red2(const float* __restrict__ pmax, const float* __restrict__ psum,
                       float* __restrict__ logZ) {
    if (threadIdx.x == 0) {
        float M = -INFINITY;
        for (int i = 0; i < 64; i++) M = fmaxf(M, pmax[i]);
        float S = 0.f;
        for (int i = 0; i < 64; i++) S += psum[i] * expf(pmax[i] - M);
        *logZ = M + logf(S);
    }
}

__global__ void k_final(float* __restrict__ out, const float* __restrict__ logZ) {
    int i = blockIdx.x * blockDim.x + threadIdx.x;
    if (i < VOCAB) out[i] -= *logZ;
}

// ---------------------------------------------------------------------------
extern "C" void kernel_launch(void* const* d_in, const int* in_sizes, int n_in,
                              void* d_out, int out_size) {
    float* sc = nullptr;
    cudaGetSymbolAddress((void**)&sc, g_scratch);

    const int*   tok    = (const int*)d_in[0];
    const float* hid    = (const float*)d_in[1];
    const float* enc    = (const float*)d_in[2];
    const float* nlg    = (const float*)d_in[3];
    const float* emb    = (const float*)d_in[4];
    const float* attn_W = (const float*)d_in[5];
    // d_in[6] = attn_b: softmax-invariant constant, unused by construction
    const float* comb_W = (const float*)d_in[7];
    const float* comb_b = (const float*)d_in[8];
    const float* fc1_W  = (const float*)d_in[9];
    const float* fc1_b  = (const float*)d_in[10];
    const float* fc2_W  = (const float*)d_in[11];
    const float* fc2_b  = (const float*)d_in[12];
    const float* Wih    = (const float*)d_in[13];
    const float* Whh    = (const float*)d_in[14];
    const float* bih    = (const float*)d_in[15];
    const float* bhh    = (const float*)d_in[16];
    const float* out_W  = (const float*)d_in[17];
    const float* out_b  = (const float*)d_in[18];
    float* out = (float*)d_out;

    float* v    = sc + OFF_V;
    float* ctx  = sc + OFF_CTX;
    float* slog = sc + OFF_SLOG;
    float* x1   = sc + OFF_X1;
    float* x2   = sc + OFF_X2;
    float* x3   = sc + OFF_X3;
    float* gi   = sc + OFF_GI;
    float* gh   = sc + OFF_GH;
    float* xo   = sc + OFF_XO;
    float* pmax = sc + OFF_PMAX;
    float* psum = sc + OFF_PSUM;
    float* logZ = sc + OFF_LOGZ;

    // 1) zero accumulators
    k_zero<<<16, 256>>>(sc);
    // 2) v = attn_W^T @ h   (attn_b drops out of the softmax)
    k_colmv<<<dim3(8, 8), 256>>>(attn_W, hid, v);
    // 3) score logits: slog[s] = enc[s,:] · v
    k_rowmv<TWO_H, false><<<S_LEN / 8, 256>>>(enc, v, nullptr, slog, S_LEN);
    // 4) softmax -> scores (in place) + attn_weights output
    k_softmax<<<1, 1024>>>(slog, out + VOCAB + H);
    // 5) context = scores^T @ enc
    k_colmv<<<dim3(8, 16), 256>>>(enc, slog, ctx);
    // 6) x1 = relu(comb_W @ [emb, ctx, nlg] + b)
    k_comb<<<H / 8, 256>>>(comb_W, comb_b, emb, tok, ctx, nlg, x1);
    // 7,8) fc1, fc2
    k_rowmv<H, true><<<H / 8, 256>>>(fc1_W, x1, fc1_b, x2, H);
    k_rowmv<H, true><<<H / 8, 256>>>(fc2_W, x2, fc2_b, x3, H);
    // 9,10) GRU input/hidden GEMVs
    k_rowmv<H, false><<<3 * H / 8, 256>>>(Wih, x3, bih, gi, 3 * H);
    k_rowmv<H, false><<<3 * H / 8, 256>>>(Whh, hid, bhh, gh, 3 * H);
    // 11) gates -> h_new (output) + xo = [h_new, nlg, emb]
    k_gate<<<1, 1024>>>(gi, gh, hid, nlg, emb, tok, xo, out + VOCAB);
    // 12) logits = out_W @ xo + out_b   (the 312 MB read)
    k_rowmv<OUT_IN, false><<<(VOCAB + 7) / 8, 256>>>(out_W, xo, out_b, out, VOCAB);
    // 13-15) log-softmax
    k_red1<<<64, 256>>>(out, pmax, psum);
    k_red2<<<1, 32>>>(pmax, psum, logZ);
    k_final<<<(VOCAB + 255) / 256, 256>>>(out, logZ);
}

// round 2
// speedup vs baseline: 1.0137x; 1.0137x over previous
#include <cuda_runtime.h>
#include <math.h>

#define H 1024
#define TWO_H 2048
#define S_LEN 2048
#define D_EMB 512
#define L_CLS 16
#define VOCAB 50257
#define OUT_IN 1552    // H + L + D
#define COMB_IN 2576   // D + 2H + L

#define NB 144         // total blocks (<= SM count -> wave-1 co-resident)
#define CHAIN_NB 64    // blocks running the serial chain
#define NTHREADS 1024

// ---------------- scratch (device globals; no allocation) ----------------
__device__ __align__(16) float g_vpart[8 * 2048];    // attn_W^T h, 8 k-chunks
__device__ __align__(16) float g_ctxpart[32 * 2048]; // scores^T enc, 32 k-chunks
__device__ __align__(16) float g_scores[2048];
__device__ __align__(16) float g_x1[1024];
__device__ __align__(16) float g_x2[1024];
__device__ __align__(16) float g_x3[1024];
__device__ __align__(16) float g_gh[3072];
__device__ __align__(16) float g_gi[3072];
__device__ __align__(16) float g_hn[1024];
__device__ float g_pm[NB], g_ps[NB], g_logZ;

// ---------------- grid barriers: one slot per use, generation-based -------
#define NBAR 12
__device__ unsigned g_cnt[NBAR];
__device__ volatile unsigned g_gen[NBAR];

__device__ __forceinline__ void gbar(int id, int n) {
    __syncthreads();
    if (threadIdx.x == 0) {
        __threadfence();
        unsigned g = g_gen[id];
        if (atomicAdd(&g_cnt[id], 1u) == (unsigned)(n - 1)) {
            g_cnt[id] = 0;
            __threadfence();
            g_gen[id] = g + 1;
        } else {
            while (g_gen[id] == g) __nanosleep(64);
        }
        __threadfence();
    }
    __syncthreads();
}

// warp-level dot of a global row against an smem vector (both float4)
__device__ __forceinline__ float warp_dot(const float4* __restrict__ wrow,
                                          const float4* __restrict__ xs,
                                          int n4, int lane) {
    float acc = 0.f;
    for (int i = lane; i < n4; i += 32) {
        float4 a = wrow[i], b = xs[i];
        acc += a.x * b.x + a.y * b.y + a.z * b.z + a.w * b.w;
    }
#pragma unroll
    for (int o = 16; o; o >>= 1) acc += __shfl_xor_sync(0xffffffffu, acc, o);
    return acc;
}

// --------------------------------------------------------------------------
__global__ void __launch_bounds__(NTHREADS, 1) fused_decoder(
    const int* __restrict__ tok, const float* __restrict__ hid,
    const float* __restrict__ enc, const float* __restrict__ nlg,
    const float* __restrict__ emb, const float* __restrict__ attn_W,
    const float* __restrict__ comb_W, const float* __restrict__ comb_b,
    const float* __restrict__ fc1_W, const float* __restrict__ fc1_b,
    const float* __restrict__ fc2_W, const float* __restrict__ fc2_b,
    const float* __restrict__ Wih, const float* __restrict__ Whh,
    const float* __restrict__ bih, const float* __restrict__ bhh,
    const float* __restrict__ out_W, const float* __restrict__ out_b,
    float* __restrict__ out)
{
    __shared__ __align__(16) float sx[2608];
    __shared__ float sr[64];
    const int b = blockIdx.x, tid = threadIdx.x;
    const int w = tid >> 5, lane = tid & 31;

    if (b >= CHAIN_NB) {
        // ============ HELPERS: constant logits part, overlapped ============
        // out[r] = out_b[r] + out_W[r, 1024:1552] . [nlg(16), emb(512)]
        int t = *tok;
        for (int i = tid; i < 528; i += NTHREADS)
            sx[i] = (i < L_CLS) ? nlg[i] : emb[(size_t)t * D_EMB + (i - L_CLS)];
        __syncthreads();
        int gw = (b - CHAIN_NB) * 32 + w;
        const int nw = (NB - CHAIN_NB) * 32;
        for (int r = gw; r < VOCAB; r += nw) {
            const float4* wr = (const float4*)(out_W + (size_t)r * OUT_IN + H);
            float acc = warp_dot(wr, (const float4*)sx, 528 / 4, lane);
            if (lane == 0) out[r] = acc + out_b[r];
        }
    } else {
        // ======================= CHAIN (64 blocks) =========================
        // S0: v-partials (attn_W^T h) on blocks 0..15; gh = Whh h on 16..63
        if (b < 16) {
            int kc = b >> 1, half = b & 1;
            if (tid < 128) sx[tid] = hid[kc * 128 + tid];
            __syncthreads();
            int col = half * 1024 + tid;
            const float* Wp = attn_W + (size_t)(kc * 128) * TWO_H + col;
            float acc = 0.f;
#pragma unroll 8
            for (int kk = 0; kk < 128; ++kk)
                acc = fmaf(Wp[(size_t)kk * TWO_H], sx[kk], acc);
            g_vpart[kc * 2048 + col] = acc;
        } else {
            for (int i = tid; i < H; i += NTHREADS) sx[i] = hid[i];
            __syncthreads();
            int lw = (b - 16) * 32 + w;  // [0,1536)
            for (int r = lw; r < 3072; r += 1536) {
                float acc = warp_dot((const float4*)(Whh + (size_t)r * H),
                                     (const float4*)sx, H / 4, lane);
                if (lane == 0) g_gh[r] = acc + bhh[r];
            }
        }
        gbar(0, CHAIN_NB);

        // S1: score logits = enc . v  (sum v-partials into smem first)
        {
            for (int i = tid; i < 2048; i += NTHREADS) {
                float s = 0.f;
#pragma unroll
                for (int k = 0; k < 8; k++) s += g_vpart[k * 2048 + i];
                sx[i] = s;
            }
            __syncthreads();
            int row = b * 32 + w;  // exactly 2048 warps
            float acc = warp_dot((const float4*)(enc + (size_t)row * TWO_H),
                                 (const float4*)sx, TWO_H / 4, lane);
            if (lane == 0) g_scores[row] = acc;
        }
        gbar(1, CHAIN_NB);

        // S2: softmax (block 0) -> scores + attn_weights output
        if (b == 0) {
            float a0 = g_scores[tid], a1 = g_scores[tid + 1024];
            float m = fmaxf(a0, a1);
#pragma unroll
            for (int o = 16; o; o >>= 1) m = fmaxf(m, __shfl_xor_sync(0xffffffffu, m, o));
            if (lane == 0) sr[w] = m;
            __syncthreads();
            if (tid == 0) { float v = sr[0]; for (int k = 1; k < 32; k++) v = fmaxf(v, sr[k]); sr[32] = v; }
            __syncthreads();
            float M = sr[32];
            float e0 = expf(a0 - M), e1 = expf(a1 - M), s = e0 + e1;
#pragma unroll
            for (int o = 16; o; o >>= 1) s += __shfl_xor_sync(0xffffffffu, s, o);
            if (lane == 0) sr[w] = s;
            __syncthreads();
            if (tid == 0) { float v = 0.f; for (int k = 0; k < 32; k++) v += sr[k]; sr[33] = v; }
            __syncthreads();
            float inv = 1.f / sr[33];
            float s0 = e0 * inv, s1 = e1 * inv;
            g_scores[tid] = s0;            g_scores[tid + 1024] = s1;
            out[VOCAB + H + tid] = s0;     out[VOCAB + H + tid + 1024] = s1;
        }
        gbar(2, CHAIN_NB);

        // S3: ctx-partials = scores^T enc  (32 k-chunks of 64 rows)
        {
            int kc = b >> 1, half = b & 1;
            if (tid < 64) sx[tid] = g_scores[kc * 64 + tid];
            __syncthreads();
            int col = half * 1024 + tid;
            const float* Ep = enc + (size_t)(kc * 64) * TWO_H + col;
            float acc = 0.f;
#pragma unroll 8
            for (int rr = 0; rr < 64; ++rr)
                acc = fmaf(Ep[(size_t)rr * TWO_H], sx[rr], acc);
            g_ctxpart[kc * 2048 + col] = acc;
        }
        gbar(3, CHAIN_NB);

        // S4: x1 = relu(comb_W . [emb, ctx, nlg] + b)   (32 active blocks)
        if (b < 32) {
            int t = *tok;
            for (int i = tid; i < COMB_IN; i += NTHREADS) {
                float v;
                if (i < D_EMB) v = emb[(size_t)t * D_EMB + i];
                else if (i < D_EMB + TWO_H) {
                    int c = i - D_EMB; float s = 0.f;
#pragma unroll
                    for (int k = 0; k < 32; k++) s += g_ctxpart[k * 2048 + c];
                    v = s;
                } else v = nlg[i - (D_EMB + TWO_H)];
                sx[i] = v;
            }
            __syncthreads();
            int row = b * 32 + w;  // < 1024
            float acc = warp_dot((const float4*)(comb_W + (size_t)row * COMB_IN),
                                 (const float4*)sx, COMB_IN / 4, lane);
            if (lane == 0) g_x1[row] = fmaxf(acc + comb_b[row], 0.f);
        }
        gbar(4, CHAIN_NB);

        // S5: fc1
        if (b < 32) {
            for (int i = tid; i < H; i += NTHREADS) sx[i] = g_x1[i];
            __syncthreads();
            int row = b * 32 + w;
            float acc = warp_dot((const float4*)(fc1_W + (size_t)row * H),
                                 (const float4*)sx, H / 4, lane);
            if (lane == 0) g_x2[row] = fmaxf(acc + fc1_b[row], 0.f);
        }
        gbar(5, CHAIN_NB);

        // S6: fc2
        if (b < 32) {
            for (int i = tid; i < H; i += NTHREADS) sx[i] = g_x2[i];
            __syncthreads();
            int row = b * 32 + w;
            float acc = warp_dot((const float4*)(fc2_W + (size_t)row * H),
                                 (const float4*)sx, H / 4, lane);
            if (lane == 0) g_x3[row] = fmaxf(acc + fc2_b[row], 0.f);
        }
        gbar(6, CHAIN_NB);

        // S7: gi = Wih . x3 + bih   (all 64 blocks, 3072 rows)
        {
            for (int i = tid; i < H; i += NTHREADS) sx[i] = g_x3[i];
            __syncthreads();
            int gw2 = b * 32 + w;  // [0,2048)
            for (int r = gw2; r < 3072; r += 2048) {
                float acc = warp_dot((const float4*)(Wih + (size_t)r * H),
                                     (const float4*)sx, H / 4, lane);
                if (lane == 0) g_gi[r] = acc + bih[r];
            }
        }
        gbar(7, CHAIN_NB);

        // S8: GRU gates -> h_new (block 0)
        if (b == 0) {
            float r = 1.f / (1.f + expf(-(g_gi[tid] + g_gh[tid])));
            float z = 1.f / (1.f + expf(-(g_gi[H + tid] + g_gh[H + tid])));
            float n = tanhf(g_gi[2 * H + tid] + r * g_gh[2 * H + tid]);
            float hn = (1.f - z) * n + z * hid[tid];
            g_hn[tid] = hn;
            out[VOCAB + tid] = hn;
        }
    }

    // ===================== FULL GRID: final logits =========================
    gbar(8, NB);
    {
        for (int i = tid; i < H; i += NTHREADS) sx[i] = g_hn[i];
        __syncthreads();
        int gw3 = b * 32 + w;  // [0, NB*32)
        float m = -INFINITY, ssum = 0.f;
        for (int r = gw3; r < VOCAB; r += NB * 32) {
            float acc = warp_dot((const float4*)(out_W + (size_t)r * OUT_IN),
                                 (const float4*)sx, H / 4, lane);
            if (lane == 0) {
                float z = out[r] + acc;   // add precomputed constant part
                out[r] = z;
                if (z > m) { ssum = ssum * expf(m - z) + 1.f; m = z; }
                else       { ssum += expf(z - m); }
            }
        }
        if (lane == 0) { sr[w] = m; sr[32 + w] = ssum; }
        __syncthreads();
        if (tid == 0) {
            float M = -INFINITY;
            for (int k = 0; k < 32; k++) M = fmaxf(M, sr[k]);
            float S = 0.f;
            for (int k = 0; k < 32; k++) S += sr[32 + k] * expf(sr[k] - M);
            g_pm[b] = M; g_ps[b] = S;
        }
    }
    gbar(9, NB);
    if (b == 0) {
        float m = (tid < NB) ? g_pm[tid] : -INFINITY;
        float s = (tid < NB) ? g_ps[tid] : 0.f;
        float mm = m;
#pragma unroll
        for (int o = 16; o; o >>= 1) mm = fmaxf(mm, __shfl_xor_sync(0xffffffffu, mm, o));
        if (lane == 0) sr[w] = mm;
        __syncthreads();
        if (tid == 0) { float v = sr[0]; for (int k = 1; k < 32; k++) v = fmaxf(v, sr[k]); sr[32] = v; }
        __syncthreads();
        float M = sr[32];
        float se = (s > 0.f) ? s * expf(m - M) : 0.f;
#pragma unroll
        for (int o = 16; o; o >>= 1) se += __shfl_xor_sync(0xffffffffu, se, o);
        if (lane == 0) sr[w] = se;
        __syncthreads();
        if (tid == 0) { float v = 0.f; for (int k = 0; k < 32; k++) v += sr[k]; g_logZ = M + logf(v); }
    }
    gbar(10, NB);
    {
        float lz = g_logZ;
        int i = b * NTHREADS + tid;
        if (i < VOCAB) out[i] -= lz;
    }
}

// --------------------------------------------------------------------------
extern "C" void kernel_launch(void* const* d_in, const int* in_sizes, int n_in,
                              void* d_out, int out_size) {
    const int*   tok    = (const int*)d_in[0];
    const float* hid    = (const float*)d_in[1];
    const float* enc    = (const float*)d_in[2];
    const float* nlg    = (const float*)d_in[3];
    const float* emb    = (const float*)d_in[4];
    const float* attn_W = (const float*)d_in[5];
    // d_in[6] = attn_b: softmax-invariant constant, drops out by construction
    const float* comb_W = (const float*)d_in[7];
    const float* comb_b = (const float*)d_in[8];
    const float* fc1_W  = (const float*)d_in[9];
    const float* fc1_b  = (const float*)d_in[10];
    const float* fc2_W  = (const float*)d_in[11];
    const float* fc2_b  = (const float*)d_in[12];
    const float* Wih    = (const float*)d_in[13];
    const float* Whh    = (const float*)d_in[14];
    const float* bih    = (const float*)d_in[15];
    const float* bhh    = (const float*)d_in[16];
    const float* out_W  = (const float*)d_in[17];
    const float* out_b  = (const float*)d_in[18];
    float* out = (float*)d_out;

    fused_decoder<<<NB, NTHREADS>>>(tok, hid, enc, nlg, emb, attn_W,
                                    comb_W, comb_b, fc1_W, fc1_b, fc2_W, fc2_b,
                                    Wih, Whh, bih, bhh, out_W, out_b, out);
}

// round 3
// speedup vs baseline: 1.1103x; 1.0954x over previous
#include <cuda_runtime.h>
#include <math.h>
#include <float.h>

#define H 1024
#define TWO_H 2048
#define S_LEN 2048
#define D_EMB 512
#define L_CLS 16
#define VOCAB 50257
#define OUT_IN 1552    // H + L + D
#define COMB_IN 2576   // D + 2H + L
#define CONST_N 528    // L + D
#define CONST_N4 132

#define NB 144
#define CHAIN_NB 64
#define NTHREADS 1024
#define NWARPS (NB * 32)

// ---------------- scratch (device globals; no allocation) ----------------
__device__ __align__(16) float g_vpart[8 * 2048];
__device__ __align__(16) float g_ctxpart[32 * 2048];
__device__ __align__(16) float g_scores[2048];
__device__ __align__(16) float g_x1[1024];
__device__ __align__(16) float g_x2[1024];
__device__ __align__(16) float g_x3[1024];
__device__ __align__(16) float g_gh[3072];
__device__ __align__(16) float g_gi[3072];
__device__ __align__(16) float g_hn[1024];
__device__ float g_pm[NB], g_ps[NB], g_logZ;
__device__ unsigned g_wq;   // work-steal chunk counter for const logits part

// ---------------- grid barriers ----------------
#define NBAR 12
__device__ unsigned g_cnt[NBAR];
__device__ volatile unsigned g_gen[NBAR];

__device__ __forceinline__ void gbar(int id, int n) {
    __syncthreads();
    if (threadIdx.x == 0) {
        __threadfence();
        unsigned g = g_gen[id];
        if (atomicAdd(&g_cnt[id], 1u) == (unsigned)(n - 1)) {
            g_cnt[id] = 0;
            __threadfence();
            g_gen[id] = g + 1;
        } else {
            while (g_gen[id] == g) __nanosleep(32);
        }
        __threadfence();
    }
    __syncthreads();
}

// ---------------- compile-time-unrolled warp dot ----------------
template<int N4>
__device__ __forceinline__ float wdot(const float4* __restrict__ wr,
                                      const float4* __restrict__ xs, int lane) {
    float acc = 0.f;
    constexpr int FULL = N4 / 32;
#pragma unroll 4
    for (int k = 0; k < FULL; k++) {
        int i = lane + k * 32;
        float4 a = wr[i], b = xs[i];
        acc += a.x * b.x + a.y * b.y + a.z * b.z + a.w * b.w;
    }
    if constexpr (N4 % 32 != 0) {
        int i = lane + FULL * 32;
        if (i < N4) {
            float4 a = wr[i], b = xs[i];
            acc += a.x * b.x + a.y * b.y + a.z * b.z + a.w * b.w;
        }
    }
#pragma unroll
    for (int o = 16; o; o >>= 1) acc += __shfl_xor_sync(0xffffffffu, acc, o);
    return acc;
}

// 4-row batched partial dots (no reduce), compile-time length
template<int N4>
__device__ __forceinline__ void quad_dot(const float4* __restrict__ W0,
                                         const float4* __restrict__ W1,
                                         const float4* __restrict__ W2,
                                         const float4* __restrict__ W3,
                                         const float4* __restrict__ xs, int lane,
                                         float& a0, float& a1, float& a2, float& a3) {
    a0 = a1 = a2 = a3 = 0.f;
    constexpr int FULL = N4 / 32;
#pragma unroll 2
    for (int k = 0; k < FULL; k++) {
        int i = lane + k * 32;
        float4 x = xs[i];
        float4 q0 = W0[i], q1 = W1[i], q2 = W2[i], q3 = W3[i];
        a0 += q0.x * x.x + q0.y * x.y + q0.z * x.z + q0.w * x.w;
        a1 += q1.x * x.x + q1.y * x.y + q1.z * x.z + q1.w * x.w;
        a2 += q2.x * x.x + q2.y * x.y + q2.z * x.z + q2.w * x.w;
        a3 += q3.x * x.x + q3.y * x.y + q3.z * x.z + q3.w * x.w;
    }
    if constexpr (N4 % 32 != 0) {
        int i = lane + FULL * 32;
        if (i < N4) {
            float4 x = xs[i];
            float4 q0 = W0[i], q1 = W1[i], q2 = W2[i], q3 = W3[i];
            a0 += q0.x * x.x + q0.y * x.y + q0.z * x.z + q0.w * x.w;
            a1 += q1.x * x.x + q1.y * x.y + q1.z * x.z + q1.w * x.w;
            a2 += q2.x * x.x + q2.y * x.y + q2.z * x.z + q2.w * x.w;
            a3 += q3.x * x.x + q3.y * x.y + q3.z * x.z + q3.w * x.w;
        }
    }
#pragma unroll
    for (int o = 16; o; o >>= 1) {
        a0 += __shfl_xor_sync(0xffffffffu, a0, o);
        a1 += __shfl_xor_sync(0xffffffffu, a1, o);
        a2 += __shfl_xor_sync(0xffffffffu, a2, o);
        a3 += __shfl_xor_sync(0xffffffffu, a3, o);
    }
}

// --------------------------------------------------------------------------
__global__ void __launch_bounds__(NTHREADS, 1) fused_decoder(
    const int* __restrict__ tok, const float* __restrict__ hid,
    const float* __restrict__ enc, const float* __restrict__ nlg,
    const float* __restrict__ emb, const float* __restrict__ attn_W,
    const float* __restrict__ comb_W, const float* __restrict__ comb_b,
    const float* __restrict__ fc1_W, const float* __restrict__ fc1_b,
    const float* __restrict__ fc2_W, const float* __restrict__ fc2_b,
    const float* __restrict__ Wih, const float* __restrict__ Whh,
    const float* __restrict__ bih, const float* __restrict__ bhh,
    const float* __restrict__ out_W, const float* __restrict__ out_b,
    float* __restrict__ out)
{
    __shared__ __align__(16) float sx[2608];
    __shared__ float sr[64];
    __shared__ int sc_chunk;
    const int b = blockIdx.x, tid = threadIdx.x;
    const int w = tid >> 5, lane = tid & 31;

    if (b < CHAIN_NB) {
        // ======================= CHAIN (64 blocks) =========================
        // S0: v-partials (attn_W^T h) on blocks 0..15; gh = Whh h on 16..63
        if (b < 16) {
            int kc = b >> 1, half = b & 1;
            if (tid < 128) sx[tid] = hid[kc * 128 + tid];
            __syncthreads();
            int col = half * 1024 + tid;
            const float* Wp = attn_W + (size_t)(kc * 128) * TWO_H + col;
            float acc = 0.f;
#pragma unroll 8
            for (int kk = 0; kk < 128; ++kk)
                acc = fmaf(Wp[(size_t)kk * TWO_H], sx[kk], acc);
            g_vpart[kc * 2048 + col] = acc;
        } else {
            for (int i = tid; i < H; i += NTHREADS) sx[i] = hid[i];
            __syncthreads();
            int lw = (b - 16) * 32 + w;  // [0,1536)
#pragma unroll
            for (int rr = 0; rr < 2; rr++) {
                int r = lw + rr * 1536;
                float acc = wdot<H / 4>((const float4*)(Whh + (size_t)r * H),
                                        (const float4*)sx, lane);
                if (lane == 0) g_gh[r] = acc + bhh[r];
            }
        }
        gbar(0, CHAIN_NB);

        // S1: score logits = enc . v
        {
            for (int i = tid; i < 2048; i += NTHREADS) {
                float s = 0.f;
#pragma unroll
                for (int k = 0; k < 8; k++) s += g_vpart[k * 2048 + i];
                sx[i] = s;
            }
            __syncthreads();
            int row = b * 32 + w;
            float acc = wdot<TWO_H / 4>((const float4*)(enc + (size_t)row * TWO_H),
                                        (const float4*)sx, lane);
            if (lane == 0) g_scores[row] = acc;
        }
        gbar(1, CHAIN_NB);

        // S2: softmax (block 0)
        if (b == 0) {
            float a0 = g_scores[tid], a1 = g_scores[tid + 1024];
            float m = fmaxf(a0, a1);
#pragma unroll
            for (int o = 16; o; o >>= 1) m = fmaxf(m, __shfl_xor_sync(0xffffffffu, m, o));
            if (lane == 0) sr[w] = m;
            __syncthreads();
            if (tid == 0) { float v = sr[0]; for (int k = 1; k < 32; k++) v = fmaxf(v, sr[k]); sr[32] = v; }
            __syncthreads();
            float M = sr[32];
            float e0 = expf(a0 - M), e1 = expf(a1 - M), s = e0 + e1;
#pragma unroll
            for (int o = 16; o; o >>= 1) s += __shfl_xor_sync(0xffffffffu, s, o);
            if (lane == 0) sr[w] = s;
            __syncthreads();
            if (tid == 0) { float v = 0.f; for (int k = 0; k < 32; k++) v += sr[k]; sr[33] = v; }
            __syncthreads();
            float inv = 1.f / sr[33];
            float s0 = e0 * inv, s1 = e1 * inv;
            g_scores[tid] = s0;            g_scores[tid + 1024] = s1;
            out[VOCAB + H + tid] = s0;     out[VOCAB + H + tid + 1024] = s1;
        }
        gbar(2, CHAIN_NB);

        // S3: ctx-partials
        {
            int kc = b >> 1, half = b & 1;
            if (tid < 64) sx[tid] = g_scores[kc * 64 + tid];
            __syncthreads();
            int col = half * 1024 + tid;
            const float* Ep = enc + (size_t)(kc * 64) * TWO_H + col;
            float acc = 0.f;
#pragma unroll 8
            for (int rr = 0; rr < 64; ++rr)
                acc = fmaf(Ep[(size_t)rr * TWO_H], sx[rr], acc);
            g_ctxpart[kc * 2048 + col] = acc;
        }
        gbar(3, CHAIN_NB);

        // S4: comb
        if (b < 32) {
            int t = *tok;
            for (int i = tid; i < COMB_IN; i += NTHREADS) {
                float v;
                if (i < D_EMB) v = emb[(size_t)t * D_EMB + i];
                else if (i < D_EMB + TWO_H) {
                    int c = i - D_EMB; float s = 0.f;
#pragma unroll
                    for (int k = 0; k < 32; k++) s += g_ctxpart[k * 2048 + c];
                    v = s;
                } else v = nlg[i - (D_EMB + TWO_H)];
                sx[i] = v;
            }
            __syncthreads();
            int row = b * 32 + w;
            float acc = wdot<COMB_IN / 4>((const float4*)(comb_W + (size_t)row * COMB_IN),
                                          (const float4*)sx, lane);
            if (lane == 0) g_x1[row] = fmaxf(acc + comb_b[row], 0.f);
        }
        gbar(4, CHAIN_NB);

        // S5: fc1
        if (b < 32) {
            for (int i = tid; i < H; i += NTHREADS) sx[i] = g_x1[i];
            __syncthreads();
            int row = b * 32 + w;
            float acc = wdot<H / 4>((const float4*)(fc1_W + (size_t)row * H),
                                    (const float4*)sx, lane);
            if (lane == 0) g_x2[row] = fmaxf(acc + fc1_b[row], 0.f);
        }
        gbar(5, CHAIN_NB);

        // S6: fc2
        if (b < 32) {
            for (int i = tid; i < H; i += NTHREADS) sx[i] = g_x2[i];
            __syncthreads();
            int row = b * 32 + w;
            float acc = wdot<H / 4>((const float4*)(fc2_W + (size_t)row * H),
                                    (const float4*)sx, lane);
            if (lane == 0) g_x3[row] = fmaxf(acc + fc2_b[row], 0.f);
        }
        gbar(6, CHAIN_NB);

        // S7: gi
        {
            for (int i = tid; i < H; i += NTHREADS) sx[i] = g_x3[i];
            __syncthreads();
            int gw2 = b * 32 + w;
            for (int r = gw2; r < 3072; r += 2048) {
                float acc = wdot<H / 4>((const float4*)(Wih + (size_t)r * H),
                                        (const float4*)sx, lane);
                if (lane == 0) g_gi[r] = acc + bih[r];
            }
        }
        gbar(7, CHAIN_NB);

        // S8: GRU gates (block 0)
        if (b == 0) {
            float r = 1.f / (1.f + expf(-(g_gi[tid] + g_gh[tid])));
            float z = 1.f / (1.f + expf(-(g_gi[H + tid] + g_gh[H + tid])));
            float n = tanhf(g_gi[2 * H + tid] + r * g_gh[2 * H + tid]);
            float hn = (1.f - z) * n + z * hid[tid];
            g_hn[tid] = hn;
            out[VOCAB + tid] = hn;
        }
    }

    // ============ ALL BLOCKS: const logits via work stealing ===============
    // out[r] = out_b[r] + out_W[r, 1024:1552] . [nlg, emb]
    // helper blocks arrive immediately; chain blocks join after the GRU.
    {
        int t = *tok;
        __syncthreads();  // sx free now (chain done with it)
        for (int i = tid; i < CONST_N; i += NTHREADS)
            sx[i] = (i < L_CLS) ? nlg[i] : emb[(size_t)t * D_EMB + (i - L_CLS)];
        __syncthreads();
        for (;;) {
            if (tid == 0) sc_chunk = (int)atomicAdd(&g_wq, 1u);
            __syncthreads();
            int c = sc_chunk;
            __syncthreads();
            if (c * 128 >= VOCAB) break;
            int r0 = c * 128 + w * 4;
            if (r0 >= VOCAB) continue;
            const float* base = out_W + (size_t)r0 * OUT_IN + H;
            if (r0 + 3 < VOCAB) {
                float a0, a1, a2, a3;
                quad_dot<CONST_N4>((const float4*)base,
                                   (const float4*)(base + OUT_IN),
                                   (const float4*)(base + 2 * OUT_IN),
                                   (const float4*)(base + 3 * OUT_IN),
                                   (const float4*)sx, lane, a0, a1, a2, a3);
                if (lane < 4) {
                    float acc = (lane == 0) ? a0 : (lane == 1) ? a1 : (lane == 2) ? a2 : a3;
                    out[r0 + lane] = acc + out_b[r0 + lane];
                }
            } else {
                for (int j = 0; j < 4; j++) {
                    int r = r0 + j;
                    if (r >= VOCAB) break;
                    float acc = wdot<CONST_N4>((const float4*)(out_W + (size_t)r * OUT_IN + H),
                                               (const float4*)sx, lane);
                    if (lane == 0) out[r] = acc + out_b[r];
                }
            }
        }
    }

    // ===================== FULL GRID: h_new logits + lse ===================
    gbar(8, NB);
    if (b == 0 && tid == 0) g_wq = 0;  // reset for next launch
    {
        for (int i = tid; i < H; i += NTHREADS) sx[i] = g_hn[i];
        __syncthreads();
        int gw3 = b * 32 + w;
        float m = -FLT_MAX, ssum = 0.f;
        for (int r0 = gw3 * 4; r0 < VOCAB; r0 += NWARPS * 4) {
            const float* base = out_W + (size_t)r0 * OUT_IN;
            if (r0 + 3 < VOCAB) {
                float a0, a1, a2, a3;
                quad_dot<H / 4>((const float4*)base,
                                (const float4*)(base + OUT_IN),
                                (const float4*)(base + 2 * OUT_IN),
                                (const float4*)(base + 3 * OUT_IN),
                                (const float4*)sx, lane, a0, a1, a2, a3);
                if (lane < 4) {
                    float acc = (lane == 0) ? a0 : (lane == 1) ? a1 : (lane == 2) ? a2 : a3;
                    int r = r0 + lane;
                    float z = out[r] + acc;
                    out[r] = z;
                    if (z > m) { ssum = ssum * expf(m - z) + 1.f; m = z; }
                    else       { ssum += expf(z - m); }
                }
            } else {
                for (int j = 0; j < 4; j++) {
                    int r = r0 + j;
                    if (r >= VOCAB) break;
                    float acc = wdot<H / 4>((const float4*)(out_W + (size_t)r * OUT_IN),
                                            (const float4*)sx, lane);
                    if (lane == j) {
                        float z = out[r] + acc;
                        out[r] = z;
                        if (z > m) { ssum = ssum * expf(m - z) + 1.f; m = z; }
                        else       { ssum += expf(z - m); }
                    }
                }
            }
        }
        // combine (m, ssum) across lanes
#pragma unroll
        for (int o = 16; o; o >>= 1) {
            float mo = __shfl_xor_sync(0xffffffffu, m, o);
            float so = __shfl_xor_sync(0xffffffffu, ssum, o);
            float nm = fmaxf(m, mo);
            ssum = ssum * expf(m - nm) + so * expf(mo - nm);
            m = nm;
        }
        if (lane == 0) { sr[w] = m; sr[32 + w] = ssum; }
        __syncthreads();
        if (tid == 0) {
            float M = -FLT_MAX;
            for (int k = 0; k < 32; k++) M = fmaxf(M, sr[k]);
            float S = 0.f;
            for (int k = 0; k < 32; k++) S += sr[32 + k] * expf(sr[k] - M);
            g_pm[b] = M; g_ps[b] = S;
        }
    }
    gbar(9, NB);
    if (b == 0) {
        float m = (tid < NB) ? g_pm[tid] : -FLT_MAX;
        float s = (tid < NB) ? g_ps[tid] : 0.f;
        float mm = m;
#pragma unroll
        for (int o = 16; o; o >>= 1) mm = fmaxf(mm, __shfl_xor_sync(0xffffffffu, mm, o));
        if (lane == 0) sr[w] = mm;
        __syncthreads();
        if (tid == 0) { float v = sr[0]; for (int k = 1; k < 32; k++) v = fmaxf(v, sr[k]); sr[32] = v; }
        __syncthreads();
        float M = sr[32];
        float se = s * expf(m - M);
#pragma unroll
        for (int o = 16; o; o >>= 1) se += __shfl_xor_sync(0xffffffffu, se, o);
        if (lane == 0) sr[w] = se;
        __syncthreads();
        if (tid == 0) { float v = 0.f; for (int k = 0; k < 32; k++) v += sr[k]; g_logZ = M + logf(v); }
    }
    gbar(10, NB);
    {
        float lz = g_logZ;
        int i = b * NTHREADS + tid;
        if (i < VOCAB) out[i] -= lz;
    }
}

// --------------------------------------------------------------------------
extern "C" void kernel_launch(void* const* d_in, const int* in_sizes, int n_in,
                              void* d_out, int out_size) {
    const int*   tok    = (const int*)d_in[0];
    const float* hid    = (const float*)d_in[1];
    const float* enc    = (const float*)d_in[2];
    const float* nlg    = (const float*)d_in[3];
    const float* emb    = (const float*)d_in[4];
    const float* attn_W = (const float*)d_in[5];
    // d_in[6] = attn_b: softmax-invariant, drops out by construction
    const float* comb_W = (const float*)d_in[7];
    const float* comb_b = (const float*)d_in[8];
    const float* fc1_W  = (const float*)d_in[9];
    const float* fc1_b  = (const float*)d_in[10];
    const float* fc2_W  = (const float*)d_in[11];
    const float* fc2_b  = (const float*)d_in[12];
    const float* Wih    = (const float*)d_in[13];
    const float* Whh    = (const float*)d_in[14];
    const float* bih    = (const float*)d_in[15];
    const float* bhh    = (const float*)d_in[16];
    const float* out_W  = (const float*)d_in[17];
    const float* out_b  = (const float*)d_in[18];
    float* out = (float*)d_out;

    fused_decoder<<<NB, NTHREADS>>>(tok, hid, enc, nlg, emb, attn_W,
                                    comb_W, comb_b, fc1_W, fc1_b, fc2_W, fc2_b,
                                    Wih, Whh, bih, bhh, out_W, out_b, out);
}

// round 5
// speedup vs baseline: 1.2178x; 1.0968x over previous
#include <cuda_runtime.h>
#include <math.h>
#include <float.h>

#define H 1024
#define TWO_H 2048
#define S_LEN 2048
#define D_EMB 512
#define L_CLS 16
#define VOCAB 50257
#define OUT_IN 1552    // H + L + D
#define COMB_IN 2576   // D + 2H + L
#define CONST_N 528    // L + D
#define CONST_N4 132

#define NB 144
#define CHAIN_NB 64
#define NTHREADS 1024

// ---------------- scratch (device globals; no allocation) ----------------
__device__ __align__(16) float g_vpart[8 * 2048];
__device__ __align__(16) float g_ctxpart[32 * 2048];
__device__ __align__(16) float g_scores[2048];
__device__ __align__(16) float g_x1[1024];
__device__ __align__(16) float g_x2[1024];
__device__ __align__(16) float g_x3[1024];
__device__ __align__(16) float g_gh[3072];
__device__ __align__(16) float g_gi[3072];
__device__ __align__(16) float g_hn[1024];
__device__ float g_pm[NB], g_ps[NB];
__device__ unsigned g_wq;      // const-part chunk queue
__device__ unsigned g_wq2;     // phase-F chunk queue

// ---------------- grid barriers ----------------
#define NBAR 10
__device__ unsigned g_cnt[NBAR];
__device__ volatile unsigned g_gen[NBAR];

__device__ __forceinline__ void gbar(int id, int n) {
    __syncthreads();
    if (threadIdx.x == 0) {
        __threadfence();
        unsigned g = g_gen[id];
        if (atomicAdd(&g_cnt[id], 1u) == (unsigned)(n - 1)) {
            g_cnt[id] = 0;
            __threadfence();
            g_gen[id] = g + 1;
        } else {
            while (g_gen[id] == g) __nanosleep(32);
        }
        __threadfence();
    }
    __syncthreads();
}

// ---------------- compile-time-unrolled warp dots ----------------
template<int N4>
__device__ __forceinline__ float wdot(const float4* __restrict__ wr,
                                      const float4* __restrict__ xs, int lane) {
    float acc = 0.f;
    constexpr int FULL = N4 / 32;
#pragma unroll 4
    for (int k = 0; k < FULL; k++) {
        int i = lane + k * 32;
        float4 a = wr[i], b = xs[i];
        acc += a.x * b.x + a.y * b.y + a.z * b.z + a.w * b.w;
    }
    if constexpr (N4 % 32 != 0) {
        int i = lane + FULL * 32;
        if (i < N4) {
            float4 a = wr[i], b = xs[i];
            acc += a.x * b.x + a.y * b.y + a.z * b.z + a.w * b.w;
        }
    }
#pragma unroll
    for (int o = 16; o; o >>= 1) acc += __shfl_xor_sync(0xffffffffu, acc, o);
    return acc;
}

// streaming (__ldcs) variant for single-use out_W data
template<int N4>
__device__ __forceinline__ float wdot_s(const float4* __restrict__ wr,
                                        const float4* __restrict__ xs, int lane) {
    float acc = 0.f;
    constexpr int FULL = N4 / 32;
#pragma unroll 4
    for (int k = 0; k < FULL; k++) {
        int i = lane + k * 32;
        float4 a = __ldcs(wr + i); float4 b = xs[i];
        acc += a.x * b.x + a.y * b.y + a.z * b.z + a.w * b.w;
    }
    if constexpr (N4 % 32 != 0) {
        int i = lane + FULL * 32;
        if (i < N4) {
            float4 a = __ldcs(wr + i); float4 b = xs[i];
            acc += a.x * b.x + a.y * b.y + a.z * b.z + a.w * b.w;
        }
    }
#pragma unroll
    for (int o = 16; o; o >>= 1) acc += __shfl_xor_sync(0xffffffffu, acc, o);
    return acc;
}

// 4-row batched streaming dots
template<int N4>
__device__ __forceinline__ void quad_dot_s(const float4* __restrict__ W0,
                                           const float4* __restrict__ W1,
                                           const float4* __restrict__ W2,
                                           const float4* __restrict__ W3,
                                           const float4* __restrict__ xs, int lane,
                                           float& a0, float& a1, float& a2, float& a3) {
    a0 = a1 = a2 = a3 = 0.f;
    constexpr int FULL = N4 / 32;
#pragma unroll 2
    for (int k = 0; k < FULL; k++) {
        int i = lane + k * 32;
        float4 x = xs[i];
        float4 q0 = __ldcs(W0 + i), q1 = __ldcs(W1 + i);
        float4 q2 = __ldcs(W2 + i), q3 = __ldcs(W3 + i);
        a0 += q0.x * x.x + q0.y * x.y + q0.z * x.z + q0.w * x.w;
        a1 += q1.x * x.x + q1.y * x.y + q1.z * x.z + q1.w * x.w;
        a2 += q2.x * x.x + q2.y * x.y + q2.z * x.z + q2.w * x.w;
        a3 += q3.x * x.x + q3.y * x.y + q3.z * x.z + q3.w * x.w;
    }
    if constexpr (N4 % 32 != 0) {
        int i = lane + FULL * 32;
        if (i < N4) {
            float4 x = xs[i];
            float4 q0 = __ldcs(W0 + i), q1 = __ldcs(W1 + i);
            float4 q2 = __ldcs(W2 + i), q3 = __ldcs(W3 + i);
            a0 += q0.x * x.x + q0.y * x.y + q0.z * x.z + q0.w * x.w;
            a1 += q1.x * x.x + q1.y * x.y + q1.z * x.z + q1.w * x.w;
            a2 += q2.x * x.x + q2.y * x.y + q2.z * x.z + q2.w * x.w;
            a3 += q3.x * x.x + q3.y * x.y + q3.z * x.z + q3.w * x.w;
        }
    }
#pragma unroll
    for (int o = 16; o; o >>= 1) {
        a0 += __shfl_xor_sync(0xffffffffu, a0, o);
        a1 += __shfl_xor_sync(0xffffffffu, a1, o);
        a2 += __shfl_xor_sync(0xffffffffu, a2, o);
        a3 += __shfl_xor_sync(0xffffffffu, a3, o);
    }
}

// --------------------------------------------------------------------------
__global__ void __launch_bounds__(NTHREADS, 1) fused_decoder(
    const int* __restrict__ tok, const float* __restrict__ hid,
    const float* __restrict__ enc, const float* __restrict__ nlg,
    const float* __restrict__ emb, const float* __restrict__ attn_W,
    const float* __restrict__ comb_W, const float* __restrict__ comb_b,
    const float* __restrict__ fc1_W, const float* __restrict__ fc1_b,
    const float* __restrict__ fc2_W, const float* __restrict__ fc2_b,
    const float* __restrict__ Wih, const float* __restrict__ Whh,
    const float* __restrict__ bih, const float* __restrict__ bhh,
    const float* __restrict__ out_W, const float* __restrict__ out_b,
    float* __restrict__ out)
{
    __shared__ __align__(16) float sx[2608];
    __shared__ float sr[64];
    __shared__ int sc_chunk;
    const int b = blockIdx.x, tid = threadIdx.x;
    const int w = tid >> 5, lane = tid & 31;

    if (b < CHAIN_NB) {
        // ======================= CHAIN (64 blocks) =========================
        // S0: v-partials (attn_W^T h) on blocks 0..15; gh = Whh h on 16..63
        if (b < 16) {
            int kc = b >> 1, half = b & 1;
            if (tid < 128) sx[tid] = hid[kc * 128 + tid];
            __syncthreads();
            int col = half * 1024 + tid;
            const float* Wp = attn_W + (size_t)(kc * 128) * TWO_H + col;
            float acc = 0.f;
#pragma unroll 8
            for (int kk = 0; kk < 128; ++kk)
                acc = fmaf(Wp[(size_t)kk * TWO_H], sx[kk], acc);
            g_vpart[kc * 2048 + col] = acc;
        } else {
            for (int i = tid; i < H; i += NTHREADS) sx[i] = hid[i];
            __syncthreads();
            int lw = (b - 16) * 32 + w;  // [0,1536)
#pragma unroll
            for (int rr = 0; rr < 2; rr++) {
                int r = lw + rr * 1536;
                float acc = wdot<H / 4>((const float4*)(Whh + (size_t)r * H),
                                        (const float4*)sx, lane);
                if (lane == 0) g_gh[r] = acc + bhh[r];
            }
        }
        gbar(0, CHAIN_NB);

        // S1: score logits = enc . v
        {
            __syncthreads();
            for (int i = tid; i < 2048; i += NTHREADS) {
                float s = 0.f;
#pragma unroll
                for (int k = 0; k < 8; k++) s += g_vpart[k * 2048 + i];
                sx[i] = s;
            }
            __syncthreads();
            int row = b * 32 + w;
            float acc = wdot<TWO_H / 4>((const float4*)(enc + (size_t)row * TWO_H),
                                        (const float4*)sx, lane);
            if (lane == 0) g_scores[row] = acc;
        }
        gbar(1, CHAIN_NB);

        // S2: softmax (block 0)
        if (b == 0) {
            float a0 = g_scores[tid], a1 = g_scores[tid + 1024];
            float m = fmaxf(a0, a1);
#pragma unroll
            for (int o = 16; o; o >>= 1) m = fmaxf(m, __shfl_xor_sync(0xffffffffu, m, o));
            if (lane == 0) sr[w] = m;
            __syncthreads();
            if (tid == 0) { float v = sr[0]; for (int k = 1; k < 32; k++) v = fmaxf(v, sr[k]); sr[32] = v; }
            __syncthreads();
            float M = sr[32];
            float e0 = expf(a0 - M), e1 = expf(a1 - M), s = e0 + e1;
#pragma unroll
            for (int o = 16; o; o >>= 1) s += __shfl_xor_sync(0xffffffffu, s, o);
            if (lane == 0) sr[w] = s;
            __syncthreads();
            if (tid == 0) { float v = 0.f; for (int k = 0; k < 32; k++) v += sr[k]; sr[33] = v; }
            __syncthreads();
            float inv = 1.f / sr[33];
            float s0 = e0 * inv, s1 = e1 * inv;
            g_scores[tid] = s0;            g_scores[tid + 1024] = s1;
            out[VOCAB + H + tid] = s0;     out[VOCAB + H + 1024 + tid] = s1;
        }
        gbar(2, CHAIN_NB);

        // S3: ctx-partials
        {
            int kc = b >> 1, half = b & 1;
            if (tid < 64) sx[tid] = g_scores[kc * 64 + tid];
            __syncthreads();
            int col = half * 1024 + tid;
            const float* Ep = enc + (size_t)(kc * 64) * TWO_H + col;
            float acc = 0.f;
#pragma unroll 8
            for (int rr = 0; rr < 64; ++rr)
                acc = fmaf(Ep[(size_t)rr * TWO_H], sx[rr], acc);
            g_ctxpart[kc * 2048 + col] = acc;
        }
        gbar(3, CHAIN_NB);

        // S4: comb
        if (b < 32) {
            int t = *tok;
            for (int i = tid; i < COMB_IN; i += NTHREADS) {
                float v;
                if (i < D_EMB) v = emb[(size_t)t * D_EMB + i];
                else if (i < D_EMB + TWO_H) {
                    int c = i - D_EMB; float s = 0.f;
#pragma unroll
                    for (int k = 0; k < 32; k++) s += g_ctxpart[k * 2048 + c];
                    v = s;
                } else v = nlg[i - (D_EMB + TWO_H)];
                sx[i] = v;
            }
            __syncthreads();
            int row = b * 32 + w;
            float acc = wdot<COMB_IN / 4>((const float4*)(comb_W + (size_t)row * COMB_IN),
                                          (const float4*)sx, lane);
            if (lane == 0) g_x1[row] = fmaxf(acc + comb_b[row], 0.f);
        }
        gbar(4, CHAIN_NB);

        // S5: fc1
        if (b < 32) {
            for (int i = tid; i < H; i += NTHREADS) sx[i] = g_x1[i];
            __syncthreads();
            int row = b * 32 + w;
            float acc = wdot<H / 4>((const float4*)(fc1_W + (size_t)row * H),
                                    (const float4*)sx, lane);
            if (lane == 0) g_x2[row] = fmaxf(acc + fc1_b[row], 0.f);
        }
        gbar(5, CHAIN_NB);

        // S6: fc2
        if (b < 32) {
            for (int i = tid; i < H; i += NTHREADS) sx[i] = g_x2[i];
            __syncthreads();
            int row = b * 32 + w;
            float acc = wdot<H / 4>((const float4*)(fc2_W + (size_t)row * H),
                                    (const float4*)sx, lane);
            if (lane == 0) g_x3[row] = fmaxf(acc + fc2_b[row], 0.f);
        }
        gbar(6, CHAIN_NB);

        // S7: gi
        {
            for (int i = tid; i < H; i += NTHREADS) sx[i] = g_x3[i];
            __syncthreads();
            int gw2 = b * 32 + w;
            for (int r = gw2; r < 3072; r += 2048) {
                float acc = wdot<H / 4>((const float4*)(Wih + (size_t)r * H),
                                        (const float4*)sx, lane);
                if (lane == 0) g_gi[r] = acc + bih[r];
            }
        }
        gbar(7, CHAIN_NB);

        // S8: GRU gates (block 0)
        if (b == 0) {
            float r = 1.f / (1.f + expf(-(g_gi[tid] + g_gh[tid])));
            float z = 1.f / (1.f + expf(-(g_gi[H + tid] + g_gh[H + tid])));
            float n = tanhf(g_gi[2 * H + tid] + r * g_gh[2 * H + tid]);
            float hn = (1.f - z) * n + z * hid[tid];
            g_hn[tid] = hn;
            out[VOCAB + tid] = hn;
        }
    }

    // ============ ALL BLOCKS: const logits via work stealing ===============
    // out[r] = out_b[r] + out_W[r, 1024:1552] . [nlg, emb]
    {
        int t = *tok;
        __syncthreads();
        for (int i = tid; i < CONST_N; i += NTHREADS)
            sx[i] = (i < L_CLS) ? nlg[i] : emb[(size_t)t * D_EMB + (i - L_CLS)];
        __syncthreads();
        for (;;) {
            if (tid == 0) sc_chunk = (int)atomicAdd(&g_wq, 1u);
            __syncthreads();
            int c = sc_chunk;
            __syncthreads();
            if (c * 128 >= VOCAB) break;
            int r0 = c * 128 + w * 4;
            if (r0 >= VOCAB) continue;
            const float* base = out_W + (size_t)r0 * OUT_IN + H;
            if (r0 + 3 < VOCAB) {
                float a0, a1, a2, a3;
                quad_dot_s<CONST_N4>((const float4*)base,
                                     (const float4*)(base + OUT_IN),
                                     (const float4*)(base + 2 * OUT_IN),
                                     (const float4*)(base + 3 * OUT_IN),
                                     (const float4*)sx, lane, a0, a1, a2, a3);
                if (lane < 4) {
                    float acc = (lane == 0) ? a0 : (lane == 1) ? a1 : (lane == 2) ? a2 : a3;
                    out[r0 + lane] = acc + out_b[r0 + lane];
                }
            } else {
                for (int j = 0; j < 4; j++) {
                    int r = r0 + j;
                    if (r >= VOCAB) break;
                    float acc = wdot_s<CONST_N4>((const float4*)(out_W + (size_t)r * OUT_IN + H),
                                                 (const float4*)sx, lane);
                    if (lane == 0) out[r] = acc + out_b[r];
                }
            }
        }
    }

    // ============== FULL GRID: h_new logits + lse (work-stolen) ============
    gbar(8, NB);
    if (b == 0 && tid == 0) g_wq = 0;  // reset for next launch
    {
        for (int i = tid; i < H; i += NTHREADS) sx[i] = g_hn[i];
        __syncthreads();
        float m = -FLT_MAX, ssum = 0.f;
        for (;;) {
            if (tid == 0) sc_chunk = (int)atomicAdd(&g_wq2, 1u);
            __syncthreads();
            int c = sc_chunk;
            __syncthreads();
            if (c * 128 >= VOCAB) break;
            int r0 = c * 128 + w * 4;
            if (r0 >= VOCAB) continue;
            const float* base = out_W + (size_t)r0 * OUT_IN;
            if (r0 + 3 < VOCAB) {
                float a0, a1, a2, a3;
                quad_dot_s<H / 4>((const float4*)base,
                                  (const float4*)(base + OUT_IN),
                                  (const float4*)(base + 2 * OUT_IN),
                                  (const float4*)(base + 3 * OUT_IN),
                                  (const float4*)sx, lane, a0, a1, a2, a3);
                if (lane < 4) {
                    float acc = (lane == 0) ? a0 : (lane == 1) ? a1 : (lane == 2) ? a2 : a3;
                    int r = r0 + lane;
                    float z = out[r] + acc;
                    out[r] = z;
                    if (z > m) { ssum = ssum * expf(m - z) + 1.f; m = z; }
                    else       { ssum += expf(z - m); }
                }
            } else {
                for (int j = 0; j < 4; j++) {
                    int r = r0 + j;
                    if (r >= VOCAB) break;
                    float acc = wdot_s<H / 4>((const float4*)(out_W + (size_t)r * OUT_IN),
                                              (const float4*)sx, lane);
                    if (lane == j) {
                        float z = out[r] + acc;
                        out[r] = z;
                        if (z > m) { ssum = ssum * expf(m - z) + 1.f; m = z; }
                        else       { ssum += expf(z - m); }
                    }
                }
            }
        }
        // merge (m, ssum) across lanes
#pragma unroll
        for (int o = 16; o; o >>= 1) {
            float mo = __shfl_xor_sync(0xffffffffu, m, o);
            float so = __shfl_xor_sync(0xffffffffu, ssum, o);
            float nm = fmaxf(m, mo);
            ssum = ssum * expf(m - nm) + so * expf(mo - nm);
            m = nm;
        }
        if (lane == 0) { sr[w] = m; sr[32 + w] = ssum; }
        __syncthreads();
        if (tid == 0) {
            float M = -FLT_MAX;
            for (int k = 0; k < 32; k++) M = fmaxf(M, sr[k]);
            float S = 0.f;
            for (int k = 0; k < 32; k++) S += sr[32 + k] * expf(sr[k] - M);
            g_pm[b] = M; g_ps[b] = S;
        }
    }
    gbar(9, NB);
    if (b == 0 && tid == 0) g_wq2 = 0;  // reset for next launch
    // every block computes logZ redundantly (saves one full-grid barrier)
    {
        if (w == 0) {
            float m = -FLT_MAX, s = 0.f;
            for (int i = lane; i < NB; i += 32) {
                float mi = g_pm[i], si = g_ps[i];
                float nm = fmaxf(m, mi);
                s = s * expf(m - nm) + si * expf(mi - nm);
                m = nm;
            }
#pragma unroll
            for (int o = 16; o; o >>= 1) {
                float mo = __shfl_xor_sync(0xffffffffu, m, o);
                float so = __shfl_xor_sync(0xffffffffu, s, o);
                float nm = fmaxf(m, mo);
                s = s * expf(m - nm) + so * expf(mo - nm);
                m = nm;
            }
            if (lane == 0) sr[0] = m + logf(s);
        }
        __syncthreads();
        float lz = sr[0];
        int i = b * NTHREADS + tid;
        if (i < VOCAB) out[i] -= lz;
    }
}

// --------------------------------------------------------------------------
extern "C" void kernel_launch(void* const* d_in, const int* in_sizes, int n_in,
                              void* d_out, int out_size) {
    const int*   tok    = (const int*)d_in[0];
    const float* hid    = (const float*)d_in[1];
    const float* enc    = (const float*)d_in[2];
    const float* nlg    = (const float*)d_in[3];
    const float* emb    = (const float*)d_in[4];
    const float* attn_W = (const float*)d_in[5];
    // d_in[6] = attn_b: softmax-invariant, drops out by construction
    const float* comb_W = (const float*)d_in[7];
    const float* comb_b = (const float*)d_in[8];
    const float* fc1_W  = (const float*)d_in[9];
    const float* fc1_b  = (const float*)d_in[10];
    const float* fc2_W  = (const float*)d_in[11];
    const float* fc2_b  = (const float*)d_in[12];
    const float* Wih    = (const float*)d_in[13];
    const float* Whh    = (const float*)d_in[14];
    const float* bih    = (const float*)d_in[15];
    const float* bhh    = (const float*)d_in[16];
    const float* out_W  = (const float*)d_in[17];
    const float* out_b  = (const float*)d_in[18];
    float* out = (float*)d_out;

    fused_decoder<<<NB, NTHREADS>>>(tok, hid, enc, nlg, emb, attn_W,
                                    comb_W, comb_b, fc1_W, fc1_b, fc2_W, fc2_b,
                                    Wih, Whh, bih, bhh, out_W, out_b, out);
}